// round 6
// baseline (speedup 1.0000x reference)
#include <cuda_runtime.h>

// Interpolate1D: stride-2 linear upsample along dim 1.
// in:  [B=16, N=8192, C=256] fp32
// out: [B, 2N, C] fp32
//   out[b, 2k,   c] = x[b, k, c]
//   out[b, 2k+1, c] = 0.5*(x[b,k,c] + x[b,k+1,c])  (k < N-1)
//   out[b, 2N-1, c] = x[b, N-1, c]
//
// Row-quad version: each thread owns one float4 column of input rows
// 4m..4m+3, loading 5 row-chunks and writing 8 contiguous output
// row-chunks (each warp writes a contiguous 4KB burst).

namespace {
constexpr int B = 16;
constexpr int N = 8192;               // divisible by 4; quads never cross batch
constexpr int C4 = 64;                // float4 per row (C=256)
constexpr unsigned TOTALT = (unsigned)B * (N / 4) * C4;  // 2,097,152
}

__device__ __forceinline__ float4 avg4(float4 a, float4 b) {
    float4 r;
    r.x = 0.5f * (a.x + b.x);
    r.y = 0.5f * (a.y + b.y);
    r.z = 0.5f * (a.z + b.z);
    r.w = 0.5f * (a.w + b.w);
    return r;
}

__global__ void __launch_bounds__(256)
interp1d_kernel(const float4* __restrict__ x, float4* __restrict__ y) {
    unsigned i = blockIdx.x * 256u + threadIdx.x;  // exact grid
    unsigned c = i & (C4 - 1);                     // float4 column 0..63
    unsigned m = i >> 6;                           // quad index: rows 4m..4m+3
    unsigned k3 = (4u * m + 3u) & (N - 1);         // row of cur3 within batch

    unsigned base = 4u * m * C4 + c;
    float4 cur0 = x[base];
    float4 cur1 = x[base + C4];
    float4 cur2 = x[base + 2u * C4];
    float4 cur3 = x[base + 3u * C4];
    float4 nxt  = (k3 < N - 1) ? x[base + 4u * C4] : cur3;

    // output rows 8m .. 8m+7 (contiguous)
    unsigned o = 8u * m * C4 + c;
    y[o]           = cur0;
    y[o + C4]      = avg4(cur0, cur1);
    y[o + 2u*C4]   = cur1;
    y[o + 3u*C4]   = avg4(cur1, cur2);
    y[o + 4u*C4]   = cur2;
    y[o + 5u*C4]   = avg4(cur2, cur3);
    y[o + 6u*C4]   = cur3;
    y[o + 7u*C4]   = avg4(cur3, nxt);
}

extern "C" void kernel_launch(void* const* d_in, const int* in_sizes, int n_in,
                              void* d_out, int out_size) {
    const float4* x = (const float4*)d_in[0];
    float4* y = (float4*)d_out;
    interp1d_kernel<<<TOTALT / 256, 256>>>(x, y);
}

// round 7
// speedup vs baseline: 1.0216x; 1.0216x over previous
#include <cuda_runtime.h>

// Interpolate1D: stride-2 linear upsample along dim 1.
// in:  [B=16, N=8192, C=256] fp32
// out: [B, 2N, C] fp32
//   out[b, 2k,   c] = x[b, k, c]
//   out[b, 2k+1, c] = 0.5*(x[b,k,c] + x[b,k+1,c])  (k < N-1)
//   out[b, 2N-1, c] = x[b, N-1, c]
//
// Final converged kernel. DRAM-bound at ~75% of 8 TB/s spec (~6 TB/s
// achieved), which six structurally distinct variants established as the
// HBM turnaround floor for this 1:2 read:write stream. This is the
// best-benching variant (R1 structure) with exact u32 indexing.

namespace {
constexpr int B = 16;
constexpr int N = 8192;
constexpr int C4 = 64;                              // float4 per row (C=256)
constexpr unsigned TOTAL4 = (unsigned)B * N * C4;   // 8,388,608 threads
}

__global__ void __launch_bounds__(256)
interp1d_kernel(const float4* __restrict__ x, float4* __restrict__ y) {
    unsigned i = blockIdx.x * 256u + threadIdx.x;   // exact grid, no bounds check
    unsigned c  = i & (C4 - 1);                     // float4 column within row
    unsigned bn = i >> 6;                           // flattened (b*N + k)
    unsigned k  = bn & (N - 1);

    float4 cur = x[i];
    float4 nxt = (k < N - 1) ? x[i + C4] : cur;

    float4 mid;
    mid.x = 0.5f * (cur.x + nxt.x);
    mid.y = 0.5f * (cur.y + nxt.y);
    mid.z = 0.5f * (cur.z + nxt.z);
    mid.w = 0.5f * (cur.w + nxt.w);

    // even output row at 2*bn, odd (midpoint) row at 2*bn+1
    unsigned o = (bn << 1) * C4 + c;
    y[o]      = cur;
    y[o + C4] = mid;
}

extern "C" void kernel_launch(void* const* d_in, const int* in_sizes, int n_in,
                              void* d_out, int out_size) {
    const float4* x = (const float4*)d_in[0];
    float4* y = (float4*)d_out;
    interp1d_kernel<<<TOTAL4 / 256, 256>>>(x, y);
}

// round 8
// speedup vs baseline: 1.0264x; 1.0047x over previous
#include <cuda_runtime.h>

// Interpolate1D: stride-2 linear upsample along dim 1.
// in:  [B=16, N=8192, C=256] fp32
// out: [B, 2N, C] fp32
//   out[b, 2k,   c] = x[b, k, c]
//   out[b, 2k+1, c] = 0.5*(x[b,k,c] + x[b,k+1,c])  (k < N-1)
//   out[b, 2N-1, c] = x[b, N-1, c]
//
// FINAL. DRAM-bound at the HBM turnaround floor (~6 TB/s, 75% of spec)
// for a 1:2 read:write interleaved stream on sm_103a. Established over
// 7 rounds / 6 structural variants: vector width, MLP, store hints,
// rows-per-thread, block size, and indexing width are all invariant
// at this floor. Best-benching structure: one float4 per thread,
// exact u32 indexing, exact-fit grid.

namespace {
constexpr int B = 16;
constexpr int N = 8192;
constexpr int C4 = 64;                              // float4 per row (C=256)
constexpr unsigned TOTAL4 = (unsigned)B * N * C4;   // 8,388,608 threads
}

__global__ void __launch_bounds__(256)
interp1d_kernel(const float4* __restrict__ x, float4* __restrict__ y) {
    unsigned i = blockIdx.x * 256u + threadIdx.x;   // exact grid, no bounds check
    unsigned c  = i & (C4 - 1);                     // float4 column within row
    unsigned bn = i >> 6;                           // flattened (b*N + k)
    unsigned k  = bn & (N - 1);

    float4 cur = x[i];
    float4 nxt = (k < N - 1) ? x[i + C4] : cur;

    float4 mid;
    mid.x = 0.5f * (cur.x + nxt.x);
    mid.y = 0.5f * (cur.y + nxt.y);
    mid.z = 0.5f * (cur.z + nxt.z);
    mid.w = 0.5f * (cur.w + nxt.w);

    // even output row at 2*bn, odd (midpoint) row at 2*bn+1
    unsigned o = (bn << 1) * C4 + c;
    y[o]      = cur;
    y[o + C4] = mid;
}

extern "C" void kernel_launch(void* const* d_in, const int* in_sizes, int n_in,
                              void* d_out, int out_size) {
    const float4* x = (const float4*)d_in[0];
    float4* y = (float4*)d_out;
    interp1d_kernel<<<TOTAL4 / 256, 256>>>(x, y);
}